// round 3
// baseline (speedup 1.0000x reference)
#include <cuda_runtime.h>

// Problem constants (fixed shapes)
#define BB 16
#define NN 25200
#define CC 80
#define TOPK 2048
#define CAP 4096
#define KW64 32   // 2048 bits = 32 x u64

// ------------------------- device scratch (no allocs allowed) ----------------
__device__ float              g_scores [BB * NN];
__device__ int                g_labels [BB * NN];
__device__ float4             g_topbox [BB * TOPK];
__device__ float              g_toparea[BB * TOPK];
__device__ float              g_topscore[BB * TOPK];
__device__ int                g_topidx [BB * TOPK];
__device__ unsigned long long g_colmask[(size_t)BB * TOPK * KW64];  // 8 MB
__device__ unsigned int       g_colnz  [BB * TOPK];

// ------------------------- K1: score max + argmax ---------------------------
// warp per (b,n) row; score_c = obj * p_c (exact fp32 mul, matches XLA),
// reduce max with first-index tiebreak; threshold at 0.25.
__global__ void k1_score_kernel(const float* __restrict__ obj,
                                const float* __restrict__ probs) {
    int gwarp = (blockIdx.x * blockDim.x + threadIdx.x) >> 5;
    int lane  = threadIdx.x & 31;
    if (gwarp >= BB * NN) return;
    const float* row = probs + (size_t)gwarp * CC;
    float o = __ldg(obj + gwarp);
    float best = -1.0f; int bi = 0;
    #pragma unroll
    for (int c = lane; c < CC; c += 32) {
        float v = __fmul_rn(o, __ldg(row + c));
        if (v > best) { best = v; bi = c; }   // ascending c -> earliest kept
    }
    #pragma unroll
    for (int off = 16; off; off >>= 1) {
        float vb = __shfl_xor_sync(0xFFFFFFFFu, best, off);
        int   ib = __shfl_xor_sync(0xFFFFFFFFu, bi,   off);
        if (vb > best || (vb == best && ib < bi)) { best = vb; bi = ib; }
    }
    if (lane == 0) {
        g_scores[gwarp] = (best > 0.25f) ? best : 0.0f;
        g_labels[gwarp] = bi;
    }
}

// ------------------------- K2: per-image top-2048 (sorted) ------------------
// Radix-select threshold on float bits (all scores >= 0), gather candidates,
// bitonic sort on composite 64-bit key: (bits<<32) | (0xFFFFFFFF - idx).
// Descending sort == descending score, ties -> smaller idx first (top_k stable).
__global__ void k2_topk_kernel(const float* __restrict__ boxes) {
    const int b   = blockIdx.x;
    const int tid = threadIdx.x;          // 1024 threads
    const float* sc = g_scores + (size_t)b * NN;

    __shared__ unsigned int hist[256];
    __shared__ unsigned int sh_prefix, sh_kneed;
    __shared__ int sh_cnt;
    __shared__ unsigned long long ck[CAP];  // 32 KB

    if (tid == 0) { sh_prefix = 0u; sh_kneed = TOPK; }

    for (int pass = 0; pass < 4; pass++) {
        int shift = 24 - pass * 8;
        if (tid < 256) hist[tid] = 0u;
        __syncthreads();
        unsigned int prefix = sh_prefix;
        unsigned int pmask  = (pass == 0) ? 0u : (0xFFFFFFFFu << (shift + 8));
        for (int n = tid; n < NN; n += 1024) {
            unsigned int key = __float_as_uint(sc[n]);
            if ((key & pmask) == prefix)
                atomicAdd(&hist[(key >> shift) & 255u], 1u);
        }
        __syncthreads();
        if (tid == 0) {
            unsigned int kneed = sh_kneed, cum = 0u;
            int v = 255;
            for (; v > 0; v--) {
                if (cum + hist[v] >= kneed) break;
                cum += hist[v];
            }
            sh_prefix = prefix | ((unsigned int)v << shift);
            sh_kneed  = kneed - cum;
        }
        __syncthreads();
    }
    const unsigned int T = sh_prefix;   // exact bits of the 2048th-largest key
    if (tid == 0) sh_cnt = 0;
    __syncthreads();

    // strictly-greater first (count < 2048 by construction, never dropped)
    for (int n = tid; n < NN; n += 1024) {
        unsigned int key = __float_as_uint(sc[n]);
        if (key > T) {
            int p = atomicAdd(&sh_cnt, 1);
            if (p < CAP)
                ck[p] = ((unsigned long long)key << 32) |
                        (unsigned long long)(0xFFFFFFFFu - (unsigned int)n);
        }
    }
    __syncthreads();
    // equal-to-threshold (sort resolves index-stable selection among ties)
    for (int n = tid; n < NN; n += 1024) {
        unsigned int key = __float_as_uint(sc[n]);
        if (key == T) {
            int p = atomicAdd(&sh_cnt, 1);
            if (p < CAP)
                ck[p] = ((unsigned long long)key << 32) |
                        (unsigned long long)(0xFFFFFFFFu - (unsigned int)n);
        }
    }
    __syncthreads();
    int total = sh_cnt < CAP ? sh_cnt : CAP;
    for (int i = total + tid; i < CAP; i += 1024)
        ck[i] = 0x00000000FFFFFFFFull;   // score 0, idx 0 (outputs zeroed anyway)
    __syncthreads();

    // bitonic sort, descending
    for (unsigned int k = 2; k <= CAP; k <<= 1) {
        for (unsigned int j = k >> 1; j > 0; j >>= 1) {
            for (unsigned int i = tid; i < CAP; i += 1024) {
                unsigned int l = i ^ j;
                if (l > i) {
                    unsigned long long a = ck[i], c = ck[l];
                    bool desc = ((i & k) == 0u);
                    if (desc ? (a < c) : (a > c)) { ck[i] = c; ck[l] = a; }
                }
            }
            __syncthreads();
        }
    }

    // emit sorted top-2048 + gathered boxes + areas
    for (int kx = tid; kx < TOPK; kx += 1024) {
        unsigned long long v = ck[kx];
        unsigned int key = (unsigned int)(v >> 32);
        int idx = (int)(0xFFFFFFFFu - (unsigned int)v);
        int o = b * TOPK + kx;
        g_topscore[o] = __uint_as_float(key);
        g_topidx[o]   = idx;
        float4 bx = __ldg(((const float4*)boxes) + (size_t)b * NN + idx);
        g_topbox[o] = bx;
        g_toparea[o] = __fmul_rn(__fsub_rn(bx.z, bx.x), __fsub_rn(bx.w, bx.y));
    }
}

// ------------------------- K3: suppression column masks ---------------------
// bit j of colmask[b][i][w] set iff j < i  &&  iou(box_i, box_j) > 0.45
__device__ __forceinline__ bool sup_test(float4 a, float aa, float4 c, float ca) {
    float ltx = fmaxf(a.x, c.x), lty = fmaxf(a.y, c.y);
    float rbx = fminf(a.z, c.z), rby = fminf(a.w, c.w);
    float wx = fmaxf(__fsub_rn(rbx, ltx), 0.0f);
    float wy = fmaxf(__fsub_rn(rby, lty), 0.0f);
    float inter = __fmul_rn(wx, wy);
    float uni   = __fsub_rn(__fadd_rn(aa, ca), inter);
    // margin fast paths; exact IEEE division (matching the reference) only near boundary
    if (inter > __fmul_rn(0.45100f, uni)) return true;
    if (inter < __fmul_rn(0.44900f, uni)) return false;
    return __fdiv_rn(inter, uni) > 0.45f;  // NaN (0/0) -> false, like the ref
}

__global__ void k3_mask_kernel() {
    // grid = BB * 8 blocks of 256 threads; each block: 256 columns of one image
    int b = blockIdx.x >> 3;
    int g = blockIdx.x & 7;
    __shared__ float4 sbox[TOPK];   // 32 KB
    __shared__ float  sarea[TOPK];  //  8 KB
    for (int i = threadIdx.x; i < TOPK; i += 256) {
        sbox[i]  = g_topbox[b * TOPK + i];
        sarea[i] = g_toparea[b * TOPK + i];
    }
    __syncthreads();
    int warp = threadIdx.x >> 5, lane = threadIdx.x & 31;
    for (int i = g * 256 + warp; i < g * 256 + 256; i += 8) {
        float4 bi = sbox[i]; float ai = sarea[i];
        int maxw = i >> 6;
        unsigned long long* col = g_colmask + (((size_t)(b * TOPK + i)) << 5);
        unsigned int nz = 0u;
        for (int w = 0; w <= maxw; w++) {
            int j0 = (w << 6) + lane;
            bool s0 = sup_test(bi, ai, sbox[j0],      sarea[j0]);
            bool s1 = sup_test(bi, ai, sbox[j0 + 32], sarea[j0 + 32]);
            unsigned int lo = __ballot_sync(0xFFFFFFFFu, s0);
            unsigned int hi = __ballot_sync(0xFFFFFFFFu, s1);
            unsigned long long word = ((unsigned long long)hi << 32) | lo;
            int rel = i - (w << 6);
            if (rel < 64) word &= ((1ull << rel) - 1ull);  // keep only j < i
            if (word) {
                nz |= (1u << w);
                if (lane == 0) col[w] = word;
            }
        }
        if (lane == 0) g_colnz[b * TOPK + i] = nz;
    }
}

// ------------------------- K4: greedy NMS fixpoint + outputs ----------------
// Jacobi iteration of keep[i] = conf[i] && !exists j<i: keep[j] && sup(j,i).
// Unique fixpoint == sequential greedy NMS; "no change" => converged exactly.
__global__ void k4_nms_out_kernel(float* __restrict__ out, int out_size) {
    int b = blockIdx.x;
    int tid = threadIdx.x;            // 1024 threads
    int lane = tid & 31, warp = tid >> 5;
    __shared__ unsigned long long kw[KW64];
    __shared__ int changed;

    int j1 = tid, j2 = tid + 1024;
    float s1 = g_topscore[b * TOPK + j1];
    float s2 = g_topscore[b * TOPK + j2];
    bool c1 = s1 > 0.0f, c2 = s2 > 0.0f;
    unsigned int nz1 = c1 ? g_colnz[b * TOPK + j1] : 0u;
    unsigned int nz2 = c2 ? g_colnz[b * TOPK + j2] : 0u;
    const unsigned long long* col1 = g_colmask + (((size_t)(b * TOPK + j1)) << 5);
    const unsigned long long* col2 = g_colmask + (((size_t)(b * TOPK + j2)) << 5);
    unsigned int* kw32 = (unsigned int*)kw;

    unsigned int ib1 = __ballot_sync(0xFFFFFFFFu, c1);
    unsigned int ib2 = __ballot_sync(0xFFFFFFFFu, c2);
    if (lane == 0) { kw32[warp] = ib1; kw32[32 + warp] = ib2; }

    bool k1 = c1, k2 = c2;
    for (int it = 0; it < TOPK + 1; it++) {
        __syncthreads();                    // kw stable & visible
        bool n1 = c1, n2 = c2;
        unsigned int m = nz1;
        while (m) { int w = __ffs(m) - 1; m &= m - 1u;
                    if (col1[w] & kw[w]) { n1 = false; break; } }
        m = nz2;
        while (m) { int w = __ffs(m) - 1; m &= m - 1u;
                    if (col2[w] & kw[w]) { n2 = false; break; } }
        __syncthreads();                    // all reads of kw done
        if (tid == 0) changed = 0;
        __syncthreads();
        unsigned int nb1 = __ballot_sync(0xFFFFFFFFu, n1);
        unsigned int nb2 = __ballot_sync(0xFFFFFFFFu, n2);
        if (lane == 0) {
            if (kw32[warp]      != nb1) { kw32[warp]      = nb1; changed = 1; }
            if (kw32[32 + warp] != nb2) { kw32[32 + warp] = nb2; changed = 1; }
        }
        __syncthreads();
        k1 = n1; k2 = n2;
        if (!changed) break;
    }

    // outputs: [boxes B*K*4][scores B*K][labels B*K] (labels cast to float)
    const int OFFS = BB * TOPK * 4;
    const int OFFL = OFFS + BB * TOPK;
    #pragma unroll
    for (int sel = 0; sel < 2; sel++) {
        int j   = sel ? j2 : j1;
        bool kk = sel ? k2 : k1;
        float s = sel ? s2 : s1;
        int o = b * TOPK + j;
        float4 bx = g_topbox[o];
        float f = kk ? 1.0f : 0.0f;
        float4 ob = make_float4(__fmul_rn(bx.x, f), __fmul_rn(bx.y, f),
                                __fmul_rn(bx.z, f), __fmul_rn(bx.w, f));
        if (4 * o + 3 < out_size) ((float4*)out)[o] = ob;
        if (OFFS + o < out_size)  out[OFFS + o] = kk ? s : 0.0f;
        if (OFFL + o < out_size) {
            int lbl = kk ? g_labels[(size_t)b * NN + g_topidx[o]] : 0;
            out[OFFL + o] = (float)lbl;
        }
    }
}

// ------------------------------- launch --------------------------------------
extern "C" void kernel_launch(void* const* d_in, const int* in_sizes, int n_in,
                              void* d_out, int out_size) {
    const float* boxes = (const float*)d_in[0];   // [16,25200,4]
    const float* obj   = (const float*)d_in[1];   // [16,25200]
    const float* probs = (const float*)d_in[2];   // [16,25200,80]
    float* out = (float*)d_out;

    // K1: warp per row
    {
        int rows = BB * NN;
        int threads = 256;
        int blocks = (rows * 32 + threads - 1) / threads;
        k1_score_kernel<<<blocks, threads>>>(obj, probs);
    }
    // K2: one block per image
    k2_topk_kernel<<<BB, 1024>>>(boxes);
    // K3: 8 blocks per image
    k3_mask_kernel<<<BB * 8, 256>>>();
    // K4: one block per image, writes outputs
    k4_nms_out_kernel<<<BB, 1024>>>(out, out_size);
}

// round 5
// speedup vs baseline: 1.5052x; 1.5052x over previous
#include <cuda_runtime.h>

// Problem constants (fixed shapes)
#define BB 16
#define NN 25200
#define CC 80
#define TOPK 2048
#define CAP 4096
#define KW64 32            // 2048 bits = 32 x u64
#define HBINS 8192
#define HSHIFT 19          // bucket = float_bits >> 19 (monotonic for keys >= 0)

// ------------------------- device scratch (no allocs allowed) ----------------
__device__ float              g_scores [BB * NN];
__device__ int                g_labels [BB * NN];
__device__ unsigned int       g_hist   [BB * HBINS];
__device__ float4             g_topbox [BB * TOPK];
__device__ float              g_toparea[BB * TOPK];
__device__ float              g_topscore[BB * TOPK];
__device__ int                g_topidx [BB * TOPK];
__device__ unsigned long long g_colmask[(size_t)BB * TOPK * KW64];  // 8 MB
__device__ unsigned int       g_colnz  [BB * TOPK];

// ------------------------- K1: score max + argmax ---------------------------
// warp per (b,n) row; score_c = obj * p_c (exact fp32 mul, matches XLA),
// reduce max with first-index tiebreak; threshold at 0.25.
// Also zeroes g_hist (blocks 0..511) for the downstream histogram kernel.
__global__ void k1_score_kernel(const float* __restrict__ obj,
                                const float* __restrict__ probs) {
    if (blockIdx.x < 512)
        g_hist[blockIdx.x * 256 + threadIdx.x] = 0u;

    int gwarp = (blockIdx.x * blockDim.x + threadIdx.x) >> 5;
    int lane  = threadIdx.x & 31;
    if (gwarp >= BB * NN) return;
    const float4* row4 = (const float4*)(probs + (size_t)gwarp * CC);
    float o = __ldg(obj + gwarp);
    float best = -1.0f; int bi = 0;
    if (lane < 20) {                       // 20 float4 = 80 classes
        float4 v = __ldg(row4 + lane);
        int c0 = lane << 2;
        float p0 = __fmul_rn(o, v.x);
        float p1 = __fmul_rn(o, v.y);
        float p2 = __fmul_rn(o, v.z);
        float p3 = __fmul_rn(o, v.w);
        best = p0; bi = c0;                             // ascending class order
        if (p1 > best) { best = p1; bi = c0 + 1; }
        if (p2 > best) { best = p2; bi = c0 + 2; }
        if (p3 > best) { best = p3; bi = c0 + 3; }
    }
    #pragma unroll
    for (int off = 16; off; off >>= 1) {
        float vb = __shfl_xor_sync(0xFFFFFFFFu, best, off);
        int   ib = __shfl_xor_sync(0xFFFFFFFFu, bi,   off);
        if (vb > best || (vb == best && ib < bi)) { best = vb; bi = ib; }
    }
    if (lane == 0) {
        g_scores[gwarp] = (best > 0.25f) ? best : 0.0f;
        g_labels[gwarp] = bi;
    }
}

// ------------------------- K2a: per-image bucket histogram ------------------
// 8 blocks per image, shared 8192-bin hist of (float_bits >> 19), merged to
// global. Monotonic bucketing => exact threshold-bucket selection downstream.
__global__ void k2a_hist_kernel() {
    int b     = blockIdx.x >> 3;
    int chunk = blockIdx.x & 7;
    __shared__ unsigned int h[HBINS];            // 32 KB
    for (int i = threadIdx.x; i < HBINS; i += 256) h[i] = 0u;
    __syncthreads();
    const float* sc = g_scores + (size_t)b * NN;
    int beg = chunk * (NN / 8);                  // 3150 per chunk, exact
    int end = beg + (NN / 8);
    for (int n = beg + threadIdx.x; n < end; n += 256) {
        unsigned int key = __float_as_uint(sc[n]);
        atomicAdd(&h[key >> HSHIFT], 1u);
    }
    __syncthreads();
    for (int i = threadIdx.x; i < HBINS; i += 256)
        if (h[i]) atomicAdd(&g_hist[b * HBINS + i], h[i]);
}

// ------------------------- K2b: select + gather + sort ----------------------
// Find threshold bucket TB (suffix count from top reaches 2048), gather all
// keys in buckets > TB (count < 2048, guaranteed kept) then == TB (ties
// region, fits CAP), bitonic-sort composite keys (bits<<32)|(~idx) descending
// == top_k's score-desc, index-ascending stable order. Emit top 2048.
__global__ void k2b_topk_kernel(const float* __restrict__ boxes) {
    const int b   = blockIdx.x;
    const int tid = threadIdx.x;                 // 1024 threads
    const float* sc = g_scores + (size_t)b * NN;

    __shared__ unsigned int partial[1024];       // 4 KB
    __shared__ unsigned long long ck[CAP];       // 32 KB
    __shared__ int sh_TB, sh_cnt;

    // per-thread partial over 8 bins
    {
        unsigned int s = 0;
        const unsigned int* hb = g_hist + b * HBINS + tid * 8;
        #pragma unroll
        for (int k = 0; k < 8; k++) s += hb[k];
        partial[tid] = s;
    }
    __syncthreads();
    if (tid == 0) {
        unsigned int cum = 0; int pb = 1023;
        for (; pb >= 0; pb--) {
            if (cum + partial[pb] >= TOPK) break;
            cum += partial[pb];
        }
        int TB = 0;
        if (pb >= 0) {
            const unsigned int* hb = g_hist + b * HBINS;
            for (int bk = pb * 8 + 7; bk >= pb * 8; bk--) {
                unsigned int c = hb[bk];
                if (cum + c >= TOPK) { TB = bk; break; }
                cum += c;
            }
        }
        sh_TB = TB;
        sh_cnt = 0;
    }
    __syncthreads();
    const unsigned int TB = (unsigned int)sh_TB;

    // gather: strictly greater bucket first (count < 2048, never dropped)
    for (int n = tid; n < NN; n += 1024) {
        unsigned int key = __float_as_uint(sc[n]);
        if ((key >> HSHIFT) > TB) {
            int p = atomicAdd(&sh_cnt, 1);
            if (p < CAP)
                ck[p] = ((unsigned long long)key << 32) |
                        (unsigned long long)(0xFFFFFFFFu - (unsigned int)n);
        }
    }
    __syncthreads();
    // threshold bucket (ties region; sort resolves exact membership/order)
    for (int n = tid; n < NN; n += 1024) {
        unsigned int key = __float_as_uint(sc[n]);
        if ((key >> HSHIFT) == TB) {
            int p = atomicAdd(&sh_cnt, 1);
            if (p < CAP)
                ck[p] = ((unsigned long long)key << 32) |
                        (unsigned long long)(0xFFFFFFFFu - (unsigned int)n);
        }
    }
    __syncthreads();
    int total = sh_cnt < CAP ? sh_cnt : CAP;
    for (int i = total + tid; i < CAP; i += 1024)
        ck[i] = 0x00000000FFFFFFFFull;           // score 0, idx 0
    __syncthreads();

    // bitonic sort, descending
    for (unsigned int k = 2; k <= CAP; k <<= 1) {
        for (unsigned int j = k >> 1; j > 0; j >>= 1) {
            #pragma unroll 4
            for (unsigned int i = tid; i < CAP; i += 1024) {
                unsigned int l = i ^ j;
                if (l > i) {
                    unsigned long long a = ck[i], c = ck[l];
                    bool desc = ((i & k) == 0u);
                    if (desc ? (a < c) : (a > c)) { ck[i] = c; ck[l] = a; }
                }
            }
            __syncthreads();
        }
    }

    // emit sorted top-2048 + gathered boxes + areas
    for (int kx = tid; kx < TOPK; kx += 1024) {
        unsigned long long v = ck[kx];
        unsigned int key = (unsigned int)(v >> 32);
        int idx = (int)(0xFFFFFFFFu - (unsigned int)v);
        int o = b * TOPK + kx;
        g_topscore[o] = __uint_as_float(key);
        g_topidx[o]   = idx;
        float4 bx = __ldg(((const float4*)boxes) + (size_t)b * NN + idx);
        g_topbox[o] = bx;
        g_toparea[o] = __fmul_rn(__fsub_rn(bx.z, bx.x), __fsub_rn(bx.w, bx.y));
    }
}

// ------------------------- K3: suppression column masks ---------------------
// bit j of colmask[b][i][w] set iff j < i  &&  iou(box_i, box_j) > 0.45
__device__ __forceinline__ bool sup_test(float4 a, float aa, float4 c, float ca) {
    float ltx = fmaxf(a.x, c.x), lty = fmaxf(a.y, c.y);
    float rbx = fminf(a.z, c.z), rby = fminf(a.w, c.w);
    float wx = fmaxf(__fsub_rn(rbx, ltx), 0.0f);
    float wy = fmaxf(__fsub_rn(rby, lty), 0.0f);
    float inter = __fmul_rn(wx, wy);
    float uni   = __fsub_rn(__fadd_rn(aa, ca), inter);
    // margin fast paths; exact IEEE division (matching the reference) only near boundary
    if (inter > __fmul_rn(0.45100f, uni)) return true;
    if (inter < __fmul_rn(0.44900f, uni)) return false;
    return __fdiv_rn(inter, uni) > 0.45f;  // NaN (0/0) -> false, like the ref
}

__global__ void k3_mask_kernel() {
    // grid = BB * 16 blocks of 256 threads; interleaved columns i ≡ g (mod 16)
    // so every block gets an identical work distribution (perfect balance).
    int b = blockIdx.x >> 4;
    int g = blockIdx.x & 15;
    __shared__ float4 sbox[TOPK];   // 32 KB
    __shared__ float  sarea[TOPK];  //  8 KB
    for (int i = threadIdx.x; i < TOPK; i += 256) {
        sbox[i]  = g_topbox[b * TOPK + i];
        sarea[i] = g_toparea[b * TOPK + i];
    }
    __syncthreads();
    int warp = threadIdx.x >> 5, lane = threadIdx.x & 31;
    for (int t = 0; t < 16; t++) {
        int i = g + 16 * warp + 128 * t;     // uniform per warp
        float4 bi = sbox[i]; float ai = sarea[i];
        int maxw = i >> 6;
        unsigned long long* col = g_colmask + (((size_t)(b * TOPK + i)) << 5);
        unsigned int nz = 0u;
        for (int w = 0; w <= maxw; w++) {
            int j0 = (w << 6) + lane;
            bool s0 = sup_test(bi, ai, sbox[j0],      sarea[j0]);
            bool s1 = sup_test(bi, ai, sbox[j0 + 32], sarea[j0 + 32]);
            unsigned int lo = __ballot_sync(0xFFFFFFFFu, s0);
            unsigned int hi = __ballot_sync(0xFFFFFFFFu, s1);
            unsigned long long word = ((unsigned long long)hi << 32) | lo;
            int rel = i - (w << 6);
            if (rel < 64) word &= ((1ull << rel) - 1ull);  // keep only j < i
            if (word) {
                nz |= (1u << w);
                if (lane == 0) col[w] = word;
            }
        }
        if (lane == 0) g_colnz[b * TOPK + i] = nz;
    }
}

// ------------------------- K4: greedy NMS fixpoint + outputs ----------------
// Jacobi iteration of keep[i] = conf[i] && !exists j<i: keep[j] && sup(j,i).
// Unique fixpoint == sequential greedy NMS; ping-pong buffers: 2 syncs/iter.
__global__ void k4_nms_out_kernel(float* __restrict__ out, int out_size) {
    int b = blockIdx.x;
    int tid = threadIdx.x;            // 1024 threads
    int lane = tid & 31, warp = tid >> 5;
    __shared__ unsigned long long kwb[2][KW64];
    __shared__ int chg[2];

    int j1 = tid, j2 = tid + 1024;
    float s1 = g_topscore[b * TOPK + j1];
    float s2 = g_topscore[b * TOPK + j2];
    bool c1 = s1 > 0.0f, c2 = s2 > 0.0f;
    unsigned int nz1 = c1 ? g_colnz[b * TOPK + j1] : 0u;
    unsigned int nz2 = c2 ? g_colnz[b * TOPK + j2] : 0u;
    const unsigned long long* col1 = g_colmask + (((size_t)(b * TOPK + j1)) << 5);
    const unsigned long long* col2 = g_colmask + (((size_t)(b * TOPK + j2)) << 5);

    unsigned int ib1 = __ballot_sync(0xFFFFFFFFu, c1);
    unsigned int ib2 = __ballot_sync(0xFFFFFFFFu, c2);
    if (lane == 0) {
        ((unsigned int*)kwb[0])[warp]      = ib1;
        ((unsigned int*)kwb[0])[32 + warp] = ib2;
    }
    if (tid < 2) chg[tid] = 0;
    __syncthreads();

    int cur = 0;
    bool k1 = c1, k2 = c2;
    for (int it = 0; it < TOPK + 1; it++) {
        int nxt = cur ^ 1;
        const unsigned long long* kw = kwb[cur];
        bool n1 = c1, n2 = c2;
        unsigned int m = nz1;
        while (m) { int w = __ffs(m) - 1; m &= m - 1u;
                    if (col1[w] & kw[w]) { n1 = false; break; } }
        m = nz2;
        while (m) { int w = __ffs(m) - 1; m &= m - 1u;
                    if (col2[w] & kw[w]) { n2 = false; break; } }
        __syncthreads();                  // SA: reads of kwb[cur]/chg done
        unsigned int nb1 = __ballot_sync(0xFFFFFFFFu, n1);
        unsigned int nb2 = __ballot_sync(0xFFFFFFFFu, n2);
        if (lane == 0) {
            unsigned int* kc = (unsigned int*)kwb[cur];
            unsigned int* kn = (unsigned int*)kwb[nxt];
            kn[warp]      = nb1;
            kn[32 + warp] = nb2;
            if (kc[warp] != nb1 || kc[32 + warp] != nb2) chg[nxt] = 1;
        }
        if (tid == 0) chg[cur] = 0;       // safe: last read of chg[cur] was pre-SA
        __syncthreads();                  // SB: kwb[nxt], chg[nxt] visible
        k1 = n1; k2 = n2;
        if (!chg[nxt]) break;
        cur = nxt;
    }

    // outputs: [boxes B*K*4][scores B*K][labels B*K] (labels cast to float)
    const int OFFS = BB * TOPK * 4;
    const int OFFL = OFFS + BB * TOPK;
    #pragma unroll
    for (int sel = 0; sel < 2; sel++) {
        int j   = sel ? j2 : j1;
        bool kk = sel ? k2 : k1;
        float s = sel ? s2 : s1;
        int o = b * TOPK + j;
        float4 bx = g_topbox[o];
        float f = kk ? 1.0f : 0.0f;
        float4 ob = make_float4(__fmul_rn(bx.x, f), __fmul_rn(bx.y, f),
                                __fmul_rn(bx.z, f), __fmul_rn(bx.w, f));
        if (4 * o + 3 < out_size) ((float4*)out)[o] = ob;
        if (OFFS + o < out_size)  out[OFFS + o] = kk ? s : 0.0f;
        if (OFFL + o < out_size) {
            int lbl = kk ? g_labels[(size_t)b * NN + g_topidx[o]] : 0;
            out[OFFL + o] = (float)lbl;
        }
    }
}

// ------------------------------- launch --------------------------------------
extern "C" void kernel_launch(void* const* d_in, const int* in_sizes, int n_in,
                              void* d_out, int out_size) {
    const float* boxes = (const float*)d_in[0];   // [16,25200,4]
    const float* obj   = (const float*)d_in[1];   // [16,25200]
    const float* probs = (const float*)d_in[2];   // [16,25200,80]
    float* out = (float*)d_out;

    // K1: warp per row (+ zero g_hist)
    {
        int rows = BB * NN;
        int threads = 256;
        int blocks = (rows * 32 + threads - 1) / threads;  // 50400
        k1_score_kernel<<<blocks, threads>>>(obj, probs);
    }
    // K2a: 8 blocks per image, bucket histogram
    k2a_hist_kernel<<<BB * 8, 256>>>();
    // K2b: one block per image, select + gather + sort
    k2b_topk_kernel<<<BB, 1024>>>(boxes);
    // K3: 16 blocks per image, interleaved columns
    k3_mask_kernel<<<BB * 16, 256>>>();
    // K4: one block per image, writes outputs
    k4_nms_out_kernel<<<BB, 1024>>>(out, out_size);
}

// round 6
// speedup vs baseline: 1.5536x; 1.0321x over previous
#include <cuda_runtime.h>

// Problem constants (fixed shapes)
#define BB 16
#define NN 25200
#define CC 80
#define TOPK 2048
#define CAP 4096
#define KW64 32            // 2048 bits = 32 x u64
#define HBINS 8192
#define HSHIFT 19          // bucket = float_bits >> 19 (monotonic for keys >= 0)

typedef unsigned long long ull;

// ------------------------- device scratch (no allocs allowed) ----------------
// g_hist is zero at module load; k2t re-zeroes it after use => every run
// (correctness call + every graph replay) sees zeros. Deterministic.
__device__ float        g_scores [BB * NN];
__device__ int          g_labels [BB * NN];
__device__ unsigned int g_hist   [BB * HBINS];
__device__ int          g_TB     [BB];
__device__ float4       g_topbox [BB * TOPK];
__device__ float        g_toparea[BB * TOPK];
__device__ float        g_topscore[BB * TOPK];
__device__ int          g_topidx [BB * TOPK];
__device__ ull          g_colmask[(size_t)BB * TOPK * KW64];  // 8 MB
__device__ unsigned int g_colnz  [BB * TOPK];

// ------------------------- K1: score max + argmax + histogram ----------------
// warp per (b,n) row; score_c = obj * p_c (exact fp32 mul, matches XLA),
// reduce max with first-index tiebreak; threshold at 0.25; bucket-histogram
// the resulting key directly (removes a separate histogram pass).
__global__ void k1_score_kernel(const float* __restrict__ obj,
                                const float* __restrict__ probs) {
    int gwarp = (blockIdx.x * blockDim.x + threadIdx.x) >> 5;
    int lane  = threadIdx.x & 31;
    if (gwarp >= BB * NN) return;
    const float4* row4 = (const float4*)(probs + (size_t)gwarp * CC);
    float o = __ldg(obj + gwarp);
    float best = -1.0f; int bi = 0;
    if (lane < 20) {                       // 20 float4 = 80 classes
        float4 v = __ldg(row4 + lane);
        int c0 = lane << 2;
        float p0 = __fmul_rn(o, v.x);
        float p1 = __fmul_rn(o, v.y);
        float p2 = __fmul_rn(o, v.z);
        float p3 = __fmul_rn(o, v.w);
        best = p0; bi = c0;                             // ascending class order
        if (p1 > best) { best = p1; bi = c0 + 1; }
        if (p2 > best) { best = p2; bi = c0 + 2; }
        if (p3 > best) { best = p3; bi = c0 + 3; }
    }
    #pragma unroll
    for (int off = 16; off; off >>= 1) {
        float vb = __shfl_xor_sync(0xFFFFFFFFu, best, off);
        int   ib = __shfl_xor_sync(0xFFFFFFFFu, bi,   off);
        if (vb > best || (vb == best && ib < bi)) { best = vb; bi = ib; }
    }
    if (lane == 0) {
        float s = (best > 0.25f) ? best : 0.0f;
        g_scores[gwarp] = s;
        g_labels[gwarp] = bi;
        int b = gwarp / NN;
        atomicAdd(&g_hist[b * HBINS + (__float_as_uint(s) >> HSHIFT)], 1u);
    }
}

// ------------------------- K2t: threshold bucket + hist reset ----------------
// One block per image. 3-level search (warp sums -> thread partials -> bins)
// keeps the serial scan to ~72 steps. Afterwards zero this image's histogram
// so the next run starts clean.
__global__ void k2t_kernel() {
    int b = blockIdx.x, tid = threadIdx.x;     // 1024 threads
    int lane = tid & 31, warp = tid >> 5;
    __shared__ unsigned int partial[1024];
    __shared__ unsigned int super[32];
    unsigned int* hb = g_hist + b * HBINS + tid * 8;
    unsigned int s = 0;
    #pragma unroll
    for (int k = 0; k < 8; k++) s += hb[k];
    partial[tid] = s;
    unsigned int ws = s;
    #pragma unroll
    for (int off = 16; off; off >>= 1) ws += __shfl_down_sync(0xFFFFFFFFu, ws, off);
    if (lane == 0) super[warp] = ws;
    __syncthreads();
    if (tid == 0) {
        unsigned int cum = 0; int w = 31;
        for (; w > 0; w--) {
            if (cum + super[w] >= TOPK) break;
            cum += super[w];
        }
        int pt = w * 32 + 31;
        for (; pt > w * 32; pt--) {
            if (cum + partial[pt] >= TOPK) break;
            cum += partial[pt];
        }
        int TB = 0;
        const unsigned int* h = g_hist + b * HBINS;
        for (int bk = pt * 8 + 7; bk >= pt * 8; bk--) {
            unsigned int c = h[bk];
            if (cum + c >= TOPK) { TB = bk; break; }
            cum += c;
        }
        g_TB[b] = TB;
    }
    __syncthreads();                            // TB reads done before reset
    #pragma unroll
    for (int k = 0; k < 8; k++) hb[k] = 0u;
}

// ------------------------- K2s: gather + bitonic sort + emit -----------------
// Gather all keys in buckets > TB (count < 2048, guaranteed kept) then == TB
// (ties region, fits CAP), bitonic-sort composite keys (bits<<32)|(~idx)
// descending == top_k's score-desc, index-ascending stable order. Emit 2048.
__device__ __forceinline__ void cmpx(ull& a, ull& b, bool desc) {
    if (desc ? (a < b) : (a > b)) { ull t = a; a = b; b = t; }
}

__global__ void k2s_topk_kernel(const float* __restrict__ boxes) {
    const int b   = blockIdx.x;
    const int tid = threadIdx.x;                 // 1024 threads
    const float* sc = g_scores + (size_t)b * NN;

    __shared__ ull ck[CAP];                      // 32 KB
    __shared__ int sh_cnt;
    if (tid == 0) sh_cnt = 0;
    __syncthreads();
    const unsigned int TB = (unsigned int)g_TB[b];

    // strictly-greater buckets first (count < 2048 by construction)
    for (int n = tid; n < NN; n += 1024) {
        unsigned int key = __float_as_uint(sc[n]);
        if ((key >> HSHIFT) > TB) {
            int p = atomicAdd(&sh_cnt, 1);
            if (p < CAP)
                ck[p] = ((ull)key << 32) | (ull)(0xFFFFFFFFu - (unsigned int)n);
        }
    }
    __syncthreads();
    // threshold bucket (ties region; sort resolves membership/order)
    for (int n = tid; n < NN; n += 1024) {
        unsigned int key = __float_as_uint(sc[n]);
        if ((key >> HSHIFT) == TB) {
            int p = atomicAdd(&sh_cnt, 1);
            if (p < CAP)
                ck[p] = ((ull)key << 32) | (ull)(0xFFFFFFFFu - (unsigned int)n);
        }
    }
    __syncthreads();
    int total = sh_cnt < CAP ? sh_cnt : CAP;
    for (int i = total + tid; i < CAP; i += 1024)
        ck[i] = 0x00000000FFFFFFFFull;           // score 0, idx 0
    __syncthreads();

    // ---- bitonic sort, descending; j=1,2 stages fused into registers ----
    const int base = tid * 4;
    {   // k=2 and k=4 entirely in registers
        ull e0 = ck[base], e1 = ck[base+1], e2 = ck[base+2], e3 = ck[base+3];
        cmpx(e0, e1, true); cmpx(e2, e3, false);        // k=2
        bool d4 = (base & 4) == 0;                      // k=4
        cmpx(e0, e2, d4); cmpx(e1, e3, d4);
        cmpx(e0, e1, d4); cmpx(e2, e3, d4);
        ck[base] = e0; ck[base+1] = e1; ck[base+2] = e2; ck[base+3] = e3;
    }
    __syncthreads();
    for (unsigned int k = 8; k <= CAP; k <<= 1) {
        for (unsigned int j = k >> 1; j >= 4; j >>= 1) {
            #pragma unroll 2
            for (unsigned int p = tid; p < CAP / 2; p += 1024) {
                unsigned int i = 2 * p - (p & (j - 1));
                unsigned int l = i + j;
                bool desc = ((i & k) == 0u);
                ull a = ck[i], c = ck[l];
                if (desc ? (a < c) : (a > c)) { ck[i] = c; ck[l] = a; }
            }
            __syncthreads();
        }
        {   // fused j=2 and j=1 (contiguous 4 share direction for k>=8)
            bool d = ((unsigned int)base & k) == 0u;
            ull e0 = ck[base], e1 = ck[base+1], e2 = ck[base+2], e3 = ck[base+3];
            cmpx(e0, e2, d); cmpx(e1, e3, d);
            cmpx(e0, e1, d); cmpx(e2, e3, d);
            ck[base] = e0; ck[base+1] = e1; ck[base+2] = e2; ck[base+3] = e3;
        }
        __syncthreads();
    }

    // emit sorted top-2048 + gathered boxes + areas
    for (int kx = tid; kx < TOPK; kx += 1024) {
        ull v = ck[kx];
        unsigned int key = (unsigned int)(v >> 32);
        int idx = (int)(0xFFFFFFFFu - (unsigned int)v);
        int o = b * TOPK + kx;
        g_topscore[o] = __uint_as_float(key);
        g_topidx[o]   = idx;
        float4 bx = __ldg(((const float4*)boxes) + (size_t)b * NN + idx);
        g_topbox[o] = bx;
        g_toparea[o] = __fmul_rn(__fsub_rn(bx.z, bx.x), __fsub_rn(bx.w, bx.y));
    }
}

// ------------------------- K3: suppression column masks ---------------------
// bit j of colmask[b][i][w] set iff j < i  &&  iou(box_i, box_j) > 0.45
__device__ __forceinline__ bool sup_test(float4 a, float aa, float4 c, float ca) {
    float ltx = fmaxf(a.x, c.x), lty = fmaxf(a.y, c.y);
    float rbx = fminf(a.z, c.z), rby = fminf(a.w, c.w);
    float wx = fmaxf(__fsub_rn(rbx, ltx), 0.0f);
    float wy = fmaxf(__fsub_rn(rby, lty), 0.0f);
    float inter = __fmul_rn(wx, wy);
    float uni   = __fsub_rn(__fadd_rn(aa, ca), inter);
    // margin fast paths; exact IEEE division (matching the reference) only near boundary
    if (inter > __fmul_rn(0.45100f, uni)) return true;
    if (inter < __fmul_rn(0.44900f, uni)) return false;
    return __fdiv_rn(inter, uni) > 0.45f;  // NaN (0/0) -> false, like the ref
}

__global__ void k3_mask_kernel() {
    // grid = BB * 32 blocks of 256 threads; interleaved columns i ≡ g (mod 32)
    // -> perfect load balance AND enough CTAs (512) to fill 148 SMs.
    int b = blockIdx.x >> 5;
    int g = blockIdx.x & 31;
    __shared__ float4 sbox[TOPK];   // 32 KB
    __shared__ float  sarea[TOPK];  //  8 KB
    for (int i = threadIdx.x; i < TOPK; i += 256) {
        sbox[i]  = g_topbox[b * TOPK + i];
        sarea[i] = g_toparea[b * TOPK + i];
    }
    __syncthreads();
    int warp = threadIdx.x >> 5, lane = threadIdx.x & 31;
    #pragma unroll
    for (int t = 0; t < 8; t++) {
        int i = g + 32 * warp + 256 * t;     // uniform per warp
        float4 bi = sbox[i]; float ai = sarea[i];
        int maxw = i >> 6;
        ull* col = g_colmask + (((size_t)(b * TOPK + i)) << 5);
        unsigned int nz = 0u;
        for (int w = 0; w <= maxw; w++) {
            int j0 = (w << 6) + lane;
            bool s0 = sup_test(bi, ai, sbox[j0],      sarea[j0]);
            bool s1 = sup_test(bi, ai, sbox[j0 + 32], sarea[j0 + 32]);
            unsigned int lo = __ballot_sync(0xFFFFFFFFu, s0);
            unsigned int hi = __ballot_sync(0xFFFFFFFFu, s1);
            ull word = ((ull)hi << 32) | lo;
            int rel = i - (w << 6);
            if (rel < 64) word &= ((1ull << rel) - 1ull);  // keep only j < i
            if (word) {
                nz |= (1u << w);
                if (lane == 0) col[w] = word;
            }
        }
        if (lane == 0) g_colnz[b * TOPK + i] = nz;
    }
}

// ------------------------- K4: greedy NMS fixpoint + outputs ----------------
// Jacobi iteration of keep[i] = conf[i] && !exists j<i: keep[j] && sup(j,i).
// Unique fixpoint == sequential greedy NMS; ping-pong buffers: 2 syncs/iter.
__global__ void k4_nms_out_kernel(float* __restrict__ out, int out_size) {
    int b = blockIdx.x;
    int tid = threadIdx.x;            // 1024 threads
    int lane = tid & 31, warp = tid >> 5;
    __shared__ ull kwb[2][KW64];
    __shared__ int chg[2];

    int j1 = tid, j2 = tid + 1024;
    float s1 = g_topscore[b * TOPK + j1];
    float s2 = g_topscore[b * TOPK + j2];
    bool c1 = s1 > 0.0f, c2 = s2 > 0.0f;
    unsigned int nz1 = c1 ? g_colnz[b * TOPK + j1] : 0u;
    unsigned int nz2 = c2 ? g_colnz[b * TOPK + j2] : 0u;
    const ull* col1 = g_colmask + (((size_t)(b * TOPK + j1)) << 5);
    const ull* col2 = g_colmask + (((size_t)(b * TOPK + j2)) << 5);

    unsigned int ib1 = __ballot_sync(0xFFFFFFFFu, c1);
    unsigned int ib2 = __ballot_sync(0xFFFFFFFFu, c2);
    if (lane == 0) {
        ((unsigned int*)kwb[0])[warp]      = ib1;
        ((unsigned int*)kwb[0])[32 + warp] = ib2;
    }
    if (tid < 2) chg[tid] = 0;
    __syncthreads();

    int cur = 0;
    bool k1 = c1, k2 = c2;
    for (int it = 0; it < TOPK + 1; it++) {
        int nxt = cur ^ 1;
        const ull* kw = kwb[cur];
        bool n1 = c1, n2 = c2;
        unsigned int m = nz1;
        while (m) { int w = __ffs(m) - 1; m &= m - 1u;
                    if (col1[w] & kw[w]) { n1 = false; break; } }
        m = nz2;
        while (m) { int w = __ffs(m) - 1; m &= m - 1u;
                    if (col2[w] & kw[w]) { n2 = false; break; } }
        __syncthreads();                  // SA: reads of kwb[cur]/chg done
        unsigned int nb1 = __ballot_sync(0xFFFFFFFFu, n1);
        unsigned int nb2 = __ballot_sync(0xFFFFFFFFu, n2);
        if (lane == 0) {
            unsigned int* kc = (unsigned int*)kwb[cur];
            unsigned int* kn = (unsigned int*)kwb[nxt];
            kn[warp]      = nb1;
            kn[32 + warp] = nb2;
            if (kc[warp] != nb1 || kc[32 + warp] != nb2) chg[nxt] = 1;
        }
        if (tid == 0) chg[cur] = 0;       // safe: last read of chg[cur] was pre-SA
        __syncthreads();                  // SB: kwb[nxt], chg[nxt] visible
        k1 = n1; k2 = n2;
        if (!chg[nxt]) break;
        cur = nxt;
    }

    // outputs: [boxes B*K*4][scores B*K][labels B*K] (labels cast to float)
    const int OFFS = BB * TOPK * 4;
    const int OFFL = OFFS + BB * TOPK;
    #pragma unroll
    for (int sel = 0; sel < 2; sel++) {
        int j   = sel ? j2 : j1;
        bool kk = sel ? k2 : k1;
        float s = sel ? s2 : s1;
        int o = b * TOPK + j;
        float4 bx = g_topbox[o];
        float f = kk ? 1.0f : 0.0f;
        float4 ob = make_float4(__fmul_rn(bx.x, f), __fmul_rn(bx.y, f),
                                __fmul_rn(bx.z, f), __fmul_rn(bx.w, f));
        if (4 * o + 3 < out_size) ((float4*)out)[o] = ob;
        if (OFFS + o < out_size)  out[OFFS + o] = kk ? s : 0.0f;
        if (OFFL + o < out_size) {
            int lbl = kk ? g_labels[(size_t)b * NN + g_topidx[o]] : 0;
            out[OFFL + o] = (float)lbl;
        }
    }
}

// ------------------------------- launch --------------------------------------
extern "C" void kernel_launch(void* const* d_in, const int* in_sizes, int n_in,
                              void* d_out, int out_size) {
    const float* boxes = (const float*)d_in[0];   // [16,25200,4]
    const float* obj   = (const float*)d_in[1];   // [16,25200]
    const float* probs = (const float*)d_in[2];   // [16,25200,80]
    float* out = (float*)d_out;

    // K1: warp per row, emits scores/labels/histogram
    {
        int rows = BB * NN;
        int threads = 256;
        int blocks = (rows * 32 + threads - 1) / threads;  // 50400
        k1_score_kernel<<<blocks, threads>>>(obj, probs);
    }
    // K2t: threshold bucket per image + histogram reset
    k2t_kernel<<<BB, 1024>>>();
    // K2s: one block per image, gather + sort + emit
    k2s_topk_kernel<<<BB, 1024>>>(boxes);
    // K3: 32 blocks per image, interleaved columns
    k3_mask_kernel<<<BB * 32, 256>>>();
    // K4: one block per image, writes outputs
    k4_nms_out_kernel<<<BB, 1024>>>(out, out_size);
}